// round 10
// baseline (speedup 1.0000x reference)
#include <cuda_runtime.h>
#include <cuda_bf16.h>
#include <math.h>

// Problem constants
#define B 4
#define T 512
#define C 256
#define C2 512
#define HEADS 4
#define MAXOFF 2
#define M (B * T)      // 2048

#define TI 64          // i-tile per block (rep)
#define TJ 64          // j-tile per block (rep)
#define NJT (T / TJ)   // 8 j-tiles
#define CK 32          // c chunk (rep)

typedef unsigned long long u64;

// Scratch (allocation-free: device globals)
__device__ float g_subj[M * C];
__device__ float g_obj[M * C];
__device__ float g_subjT[C * M];                // [c][m] transposed
__device__ float g_objT[C * M];
__device__ float g_part[M * NJT * HEADS];       // partial exp-sums per j-tile
__device__ float g_swow[2 * M * HEADS];         // Sw rows 0..M-1, Ow rows M..2M-1

// packed f32x2 helpers
static __device__ __forceinline__ u64 fma2(u64 a, u64 b, u64 c) {
    u64 r; asm("fma.rn.f32x2 %0, %1, %2, %3;" : "=l"(r) : "l"(a), "l"(b), "l"(c)); return r;
}
static __device__ __forceinline__ float2 unpack2(u64 v) {
    float2 r; asm("mov.b64 {%0, %1}, %2;" : "=f"(r.x), "=f"(r.y) : "l"(v)); return r;
}
// packed min: operands pre-paired from LDS, result feeds fma2
static __device__ __forceinline__ u64 fmin2(u64 a, u64 b) {
    union { u64 v; float2 f; } ua, ub, uc;
    ua.v = a; ub.v = b;
    uc.f.x = fminf(ua.f.x, ub.f.x);
    uc.f.y = fminf(ua.f.y, ub.f.y);
    return uc.v;
}

// ---------------------------------------------------------------------------
// Kernel 1: max-pool along channel (window 5, pad 2) + concat -> x_new
// ---------------------------------------------------------------------------
__global__ void pool_concat_kernel(const float* __restrict__ x,
                                   float* __restrict__ xnew) {
    int idx = blockIdx.x * 256 + threadIdx.x;
    if (idx >= M * C2) return;
    int cc = idx & (C2 - 1);
    int bt = idx >> 9;
    const float* xr = x + bt * C;
    float v;
    if (cc < C) {
        int lo = cc - MAXOFF; if (lo < 0) lo = 0;
        int hi = cc + MAXOFF; if (hi > C - 1) hi = C - 1;
        v = -INFINITY;
        #pragma unroll 5
        for (int c = lo; c <= hi; c++) v = fmaxf(v, xr[c]);
    } else {
        v = xr[cc - C];
    }
    xnew[idx] = v;
}

// ---------------------------------------------------------------------------
// Kernel 2: both projection GEMMs; writes normal [m][n] AND transposed [n][m].
// ---------------------------------------------------------------------------
__global__ void gemm_kernel(const float* __restrict__ A,
                            const float* __restrict__ W0,
                            const float* __restrict__ b0,
                            const float* __restrict__ W1,
                            const float* __restrict__ b1,
                            float* __restrict__ out0,
                            float* __restrict__ out1,
                            float* __restrict__ outT0,
                            float* __restrict__ outT1) {
    const int N = C;
    const int K = C2;

    const float* W    = blockIdx.z ? W1 : W0;
    const float* bias = blockIdx.z ? b1 : b0;
    float* out        = blockIdx.z ? out1 : out0;
    float* outT       = blockIdx.z ? outT1 : outT0;

    __shared__ float As[16][68];
    __shared__ float Ws[16][64];

    int tid = threadIdx.x;
    int tx = tid & 15;
    int ty = tid >> 4;
    int bm = blockIdx.y * 64;
    int bn = blockIdx.x * 64;

    float acc[4][4];
    #pragma unroll
    for (int i = 0; i < 4; i++)
        #pragma unroll
        for (int j = 0; j < 4; j++) acc[i][j] = 0.0f;

    for (int k0 = 0; k0 < K; k0 += 16) {
        #pragma unroll
        for (int l = 0; l < 4; l++) {
            int idx = tid + l * 256;
            int m = idx >> 4, ka = idx & 15;
            As[ka][m] = A[(bm + m) * K + k0 + ka];
            int n2 = idx & 63, kw = idx >> 6;
            Ws[kw][n2] = W[(k0 + kw) * N + bn + n2];
        }
        __syncthreads();
        #pragma unroll
        for (int k = 0; k < 16; k++) {
            float a[4], w[4];
            #pragma unroll
            for (int i = 0; i < 4; i++) a[i] = As[k][ty * 4 + i];
            float4 wv = *(const float4*)&Ws[k][tx * 4];
            w[0] = wv.x; w[1] = wv.y; w[2] = wv.z; w[3] = wv.w;
            #pragma unroll
            for (int i = 0; i < 4; i++)
                #pragma unroll
                for (int j = 0; j < 4; j++)
                    acc[i][j] += a[i] * w[j];
        }
        __syncthreads();
    }

    float4 bv = *(const float4*)&bias[bn + tx * 4];
    float bb[4] = {bv.x, bv.y, bv.z, bv.w};
    #pragma unroll
    for (int i = 0; i < 4; i++) {
        float4 o;
        o.x = acc[i][0] + bb[0];
        o.y = acc[i][1] + bb[1];
        o.z = acc[i][2] + bb[2];
        o.w = acc[i][3] + bb[3];
        *(float4*)&out[(bm + ty * 4 + i) * N + bn + tx * 4] = o;
    }
    // transposed write: for each n (4 of them), a float4 over 4 consecutive m
    #pragma unroll
    for (int j = 0; j < 4; j++) {
        float4 o;
        o.x = acc[0][j] + bb[j];
        o.y = acc[1][j] + bb[j];
        o.z = acc[2][j] + bb[j];
        o.w = acc[3][j] + bb[j];
        *(float4*)&outT[(size_t)(bn + tx * 4 + j) * M + bm + ty * 4] = o;
    }
}

// ---------------------------------------------------------------------------
// Kernel 2b: Sw[j,h] = subj[j,:] @ W_t  and  Ow[i,h] = obj[i,:] @ W_t.
// ---------------------------------------------------------------------------
__global__ void __launch_bounds__(128)
swow_kernel(const float* __restrict__ subj,
            const float* __restrict__ obj,
            const float* __restrict__ W_t,
            float* __restrict__ swow) {
    int gw = (blockIdx.x * 128 + threadIdx.x) >> 5;   // 0..4095
    int lane = threadIdx.x & 31;
    const float* src = (gw < M) ? subj : obj;
    int row = gw & (M - 1);

    float4 a = make_float4(0.f, 0.f, 0.f, 0.f);
    const float4* wt4 = (const float4*)W_t;
    #pragma unroll
    for (int c = lane; c < C; c += 32) {
        float s = src[row * C + c];
        float4 w = wt4[c];
        a.x += s * w.x; a.y += s * w.y; a.z += s * w.z; a.w += s * w.w;
    }
    #pragma unroll
    for (int m = 16; m >= 1; m >>= 1) {
        a.x += __shfl_xor_sync(0xffffffffu, a.x, m);
        a.y += __shfl_xor_sync(0xffffffffu, a.y, m);
        a.z += __shfl_xor_sync(0xffffffffu, a.z, m);
        a.w += __shfl_xor_sync(0xffffffffu, a.w, m);
    }
    if (lane == 0) ((float4*)swow)[gw] = a;
}

// ---------------------------------------------------------------------------
// Kernel 3a: rep = Sw[j] + Ow[i] + b - 2*sum_c min(s,o)*w, j-pair packed.
// 256 threads = 16 tx (j quads) x 16 ty (i quads); tile 64i x 64j.
// acc[4i][2jp][4h] = 32 u64 = 64 regs. o/w duplicated in smem (pre-paired).
// Grid = 256 blocks -> single wave at 2 blocks/SM (25KB smem, <=128 regs).
// ---------------------------------------------------------------------------
__global__ void __launch_bounds__(256, 2)
rep_exp_kernel(const float* __restrict__ subjT,
               const float* __restrict__ objT,
               const float* __restrict__ W_t,
               const float* __restrict__ b_t,
               const float* __restrict__ swow,
               float* __restrict__ attn,
               float* __restrict__ part) {
    __shared__ float s_sh[CK * 64];     // [c][j]         8KB
    __shared__ float o_sh[CK * 128];    // [c][2i dup]   16KB
    __shared__ float w_sh[CK * 8];      // [c][2h dup] = -2*W_t   1KB

    const int tid = threadIdx.x;
    const int tx = tid & 15;           // j quad (j = 4tx..4tx+3)
    const int ty = tid >> 4;           // i quad (i = 4ty..4ty+3), 0..15
    const int jt = blockIdx.x;
    const int j0 = jt * TJ;
    const int i0 = blockIdx.y * TI;
    const int b  = blockIdx.z;

    u64 acc[4][2][4];
    #pragma unroll
    for (int p = 0; p < 4; p++)
        #pragma unroll
        for (int qq = 0; qq < 2; qq++)
            #pragma unroll
            for (int h = 0; h < 4; h++) acc[p][qq][h] = 0ULL;

    const int sbase_j = b * T + j0;
    const int sbase_i = b * T + i0;

    for (int ck = 0; ck < C / CK; ck++) {
        const int cbase = ck * CK;
        // s: [c][j] 32x64 floats, coalesced from subjT
        #pragma unroll
        for (int l = 0; l < 2; l++) {
            int t = tid + l * 256;
            int c = t >> 4, jg = t & 15;
            float4 sv = *(const float4*)&subjT[(size_t)(cbase + c) * M + sbase_j + 4 * jg];
            *(float4*)&s_sh[c * 64 + 4 * jg] = sv;
        }
        // o: [c][2i dup] from objT (32 c x 64 i -> 128 dup floats per c)
        #pragma unroll
        for (int l = 0; l < 4; l++) {
            int t = tid + l * 256;
            int c = t >> 5, ig = t & 31;
            float2 ov = *(const float2*)&objT[(size_t)(cbase + c) * M + sbase_i + 2 * ig];
            *(float4*)&o_sh[c * 128 + 4 * ig] = make_float4(ov.x, ov.x, ov.y, ov.y);
        }
        // w: [c][2h dup] = -2*W_t
        if (tid < 64) {
            int c = tid >> 1, hh = tid & 1;
            float2 wv = *(const float2*)&W_t[(cbase + c) * 4 + 2 * hh];
            *(float4*)&w_sh[c * 8 + 4 * hh] =
                make_float4(-2.f * wv.x, -2.f * wv.x, -2.f * wv.y, -2.f * wv.y);
        }
        __syncthreads();

        #pragma unroll 4
        for (int c = 0; c < CK; c++) {
            ulonglong2 S  = *(const ulonglong2*)&s_sh[c * 64 + 4 * tx];
            ulonglong2 O0 = *(const ulonglong2*)&o_sh[c * 128 + 8 * ty];
            ulonglong2 O1 = *(const ulonglong2*)&o_sh[c * 128 + 8 * ty + 4];
            ulonglong2 W0 = *(const ulonglong2*)&w_sh[c * 8];
            ulonglong2 W1 = *(const ulonglong2*)&w_sh[c * 8 + 4];
            u64 op[4] = {O0.x, O0.y, O1.x, O1.y};
            #pragma unroll
            for (int p = 0; p < 4; p++) {
                u64 m0 = fmin2(S.x, op[p]);
                acc[p][0][0] = fma2(m0, W0.x, acc[p][0][0]);
                acc[p][0][1] = fma2(m0, W0.y, acc[p][0][1]);
                acc[p][0][2] = fma2(m0, W1.x, acc[p][0][2]);
                acc[p][0][3] = fma2(m0, W1.y, acc[p][0][3]);
                u64 m1 = fmin2(S.y, op[p]);
                acc[p][1][0] = fma2(m1, W0.x, acc[p][1][0]);
                acc[p][1][1] = fma2(m1, W0.y, acc[p][1][1]);
                acc[p][1][2] = fma2(m1, W1.x, acc[p][1][2]);
                acc[p][1][3] = fma2(m1, W1.y, acc[p][1][3]);
            }
        }
        __syncthreads();
    }

    // Epilogue: z = relu(Sw[j] + Ow[i] + b + acc), e = exp(z)
    const float4 btv = *(const float4*)b_t;
    const float4* sw4 = (const float4*)swow;              // rows 0..M-1
    const float4* ow4 = (const float4*)swow + M;          // rows M..

    float4 swv[4];
    #pragma unroll
    for (int k = 0; k < 4; k++) swv[k] = sw4[b * T + j0 + 4 * tx + k];

    #pragma unroll
    for (int p = 0; p < 4; p++) {
        int i = i0 + 4 * ty + p;
        float4 owv = ow4[b * T + i];
        float base_x = owv.x + btv.x;
        float base_y = owv.y + btv.y;
        float base_z = owv.z + btv.z;
        float base_w = owv.w + btv.w;
        float4 ps = make_float4(0.f, 0.f, 0.f, 0.f);
        #pragma unroll
        for (int qq = 0; qq < 2; qq++) {
            float2 f0 = unpack2(acc[p][qq][0]);
            float2 f1 = unpack2(acc[p][qq][1]);
            float2 f2 = unpack2(acc[p][qq][2]);
            float2 f3 = unpack2(acc[p][qq][3]);
            #pragma unroll
            for (int k = 0; k < 2; k++) {
                int jj = 2 * qq + k;
                int j = j0 + 4 * tx + jj;
                float4 sv = swv[jj];
                float4 ev;
                float a0 = k ? f0.y : f0.x;
                float a1 = k ? f1.y : f1.x;
                float a2 = k ? f2.y : f2.x;
                float a3 = k ? f3.y : f3.x;
                ev.x = __expf(fmaxf(a0 + sv.x + base_x, 0.0f));
                ev.y = __expf(fmaxf(a1 + sv.y + base_y, 0.0f));
                ev.z = __expf(fmaxf(a2 + sv.z + base_z, 0.0f));
                ev.w = __expf(fmaxf(a3 + sv.w + base_w, 0.0f));
                *(float4*)&attn[(((size_t)(b * T + i)) * T + j) * HEADS] = ev;
                ps.x += ev.x; ps.y += ev.y; ps.z += ev.z; ps.w += ev.w;
            }
        }
        // reduce across the 16 tx lanes of the half-warp
        #pragma unroll
        for (int m = 8; m >= 1; m >>= 1) {
            ps.x += __shfl_xor_sync(0xffffffffu, ps.x, m);
            ps.y += __shfl_xor_sync(0xffffffffu, ps.y, m);
            ps.z += __shfl_xor_sync(0xffffffffu, ps.z, m);
            ps.w += __shfl_xor_sync(0xffffffffu, ps.w, m);
        }
        if (tx == 0)
            *(float4*)&part[((size_t)(b * T + i) * NJT + jt) * HEADS] = ps;
    }
}

// ---------------------------------------------------------------------------
// Kernel 3b: fused denominator (one-warp shfl reduce) + normalize + mask.
// ---------------------------------------------------------------------------
__global__ void __launch_bounds__(128)
normalize_kernel(const float* __restrict__ part,
                 const int* __restrict__ mask,
                 float* __restrict__ attn) {
    __shared__ float sinv[4];
    const int bi = blockIdx.x;         // b*T + i
    const int tid = threadIdx.x;

    if (tid < 32) {
        float v = part[bi * (NJT * HEADS) + tid];   // 32 contiguous floats
        v += __shfl_xor_sync(0xffffffffu, v, 4);
        v += __shfl_xor_sync(0xffffffffu, v, 8);
        v += __shfl_xor_sync(0xffffffffu, v, 16);
        if (tid < 4) sinv[tid] = 1.0f / v;
    }
    __syncthreads();

    const float4 iv = make_float4(sinv[0], sinv[1], sinv[2], sinv[3]);
    const int mi = mask[bi];
    const int b = bi >> 9;
    float4* arow = (float4*)attn + (size_t)bi * T;

    #pragma unroll
    for (int r = 0; r < 4; r++) {
        int j = tid + r * 128;
        float4 v = arow[j];
        int mj = mask[b * T + j];
        float kill = (mi && mj) ? 0.0f : 1.0f;
        v.x *= iv.x * kill;
        v.y *= iv.y * kill;
        v.z *= iv.z * kill;
        v.w *= iv.w * kill;
        arow[j] = v;
    }
}

// ---------------------------------------------------------------------------
extern "C" void kernel_launch(void* const* d_in, const int* in_sizes, int n_in,
                              void* d_out, int out_size) {
    const float* x      = (const float*)d_in[0];
    const float* W_subj = (const float*)d_in[1];
    const float* b_subj = (const float*)d_in[2];
    const float* W_obj  = (const float*)d_in[3];
    const float* b_obj  = (const float*)d_in[4];
    const float* W_t    = (const float*)d_in[5];
    const float* b_t    = (const float*)d_in[6];
    const int*   mask   = (const int*)d_in[7];

    float* out   = (float*)d_out;
    float* xnew  = out;                          // (B,T,2C)
    float* attn  = out + (size_t)M * C2;         // (B,T,T,HEADS)

    float *subj, *obj, *subjT, *objT, *part, *swow;
    cudaGetSymbolAddress((void**)&subj, g_subj);
    cudaGetSymbolAddress((void**)&obj, g_obj);
    cudaGetSymbolAddress((void**)&subjT, g_subjT);
    cudaGetSymbolAddress((void**)&objT, g_objT);
    cudaGetSymbolAddress((void**)&part, g_part);
    cudaGetSymbolAddress((void**)&swow, g_swow);

    pool_concat_kernel<<<(M * C2 + 255) / 256, 256>>>(x, xnew);

    dim3 gg(C / 64, M / 64, 2);   // (4, 32, 2)
    gemm_kernel<<<gg, 256>>>(xnew, W_subj, b_subj, W_obj, b_obj,
                             subj, obj, subjT, objT);

    swow_kernel<<<(2 * M) / 4, 128>>>(subj, obj, W_t, swow);

    dim3 ga(T / TJ, T / TI, B);         // (8, 8, 4) = 256 blocks
    rep_exp_kernel<<<ga, 256>>>(subjT, objT, W_t, b_t, swow, attn, part);

    normalize_kernel<<<M, 128>>>(part, mask, attn);
}

// round 11
// speedup vs baseline: 1.2388x; 1.2388x over previous
#include <cuda_runtime.h>
#include <cuda_bf16.h>
#include <math.h>

// Problem constants
#define B 4
#define T 512
#define C 256
#define C2 512
#define HEADS 4
#define MAXOFF 2
#define M (B * T)      // 2048

#define TI 32          // i-tile per block (rep)
#define TJ 64          // j-tile per block (rep)
#define NJT (T / TJ)   // 8 j-tiles
#define CK 128         // c chunk (rep)

typedef unsigned long long u64;

// Scratch (allocation-free: device globals)
__device__ float g_subj[M * C];
__device__ float g_obj[M * C];
__device__ float g_part[M * NJT * HEADS];       // partial exp-sums per j-tile
__device__ float g_swow[2 * M * HEADS];         // Sw rows 0..M-1, Ow rows M..

// packed f32x2 helpers
static __device__ __forceinline__ u64 fma2(u64 a, u64 b, u64 c) {
    u64 r; asm("fma.rn.f32x2 %0, %1, %2, %3;" : "=l"(r) : "l"(a), "l"(b), "l"(c)); return r;
}
static __device__ __forceinline__ float2 unpack2(u64 v) {
    float2 r; asm("mov.b64 {%0, %1}, %2;" : "=f"(r.x), "=f"(r.y) : "l"(v)); return r;
}
static __device__ __forceinline__ u64 pack2(float lo, float hi) {
    u64 r; asm("mov.b64 %0, {%1, %2};" : "=l"(r) : "f"(lo), "f"(hi)); return r;
}
// packed min (FMNMX on ALU pipe); union form lets ptxas pair-allocate
static __device__ __forceinline__ u64 fmin2(u64 a, u64 b) {
    union { u64 v; float2 f; } ua, ub, uc;
    ua.v = a; ub.v = b;
    uc.f.x = fminf(ua.f.x, ub.f.x);
    uc.f.y = fminf(ua.f.y, ub.f.y);
    return uc.v;
}

// ---------------------------------------------------------------------------
// Kernel 1: max-pool along channel (window 5, pad 2) + concat -> x_new
// ---------------------------------------------------------------------------
__global__ void pool_concat_kernel(const float* __restrict__ x,
                                   float* __restrict__ xnew) {
    int idx = blockIdx.x * 256 + threadIdx.x;
    if (idx >= M * C2) return;
    int cc = idx & (C2 - 1);
    int bt = idx >> 9;
    const float* xr = x + bt * C;
    float v;
    if (cc < C) {
        int lo = cc - MAXOFF; if (lo < 0) lo = 0;
        int hi = cc + MAXOFF; if (hi > C - 1) hi = C - 1;
        v = -INFINITY;
        #pragma unroll 5
        for (int c = lo; c <= hi; c++) v = fmaxf(v, xr[c]);
    } else {
        v = xr[cc - C];
    }
    xnew[idx] = v;
}

// ---------------------------------------------------------------------------
// Kernel 2: projection GEMMs, m-packed f32x2.
// Tile 64m x 64n, 128 threads (tx 0..15 = n-quad, ty 0..7 = m-octet).
// A-pairs come free from As[k][m]; W dup'd in registers (2 MOV/pair).
// acc[4 m-pairs][4 n] = 16 u64.
// ---------------------------------------------------------------------------
__global__ void __launch_bounds__(128)
gemm_kernel(const float* __restrict__ A,
            const float* __restrict__ W0,
            const float* __restrict__ b0,
            const float* __restrict__ W1,
            const float* __restrict__ b1,
            float* __restrict__ out0,
            float* __restrict__ out1) {
    __shared__ float As[16 * 68];   // [k][m], stride 68
    __shared__ float Ws[16 * 68];   // [k][n], stride 68

    const float* W    = blockIdx.z ? W1 : W0;
    const float* bias = blockIdx.z ? b1 : b0;
    float* out        = blockIdx.z ? out1 : out0;

    const int tid = threadIdx.x;
    const int tx = tid & 15;           // n quad: n = 4tx..4tx+3
    const int ty = tid >> 4;           // m octet: m = 8ty..8ty+7  (0..7)
    const int bm = blockIdx.y * 64;
    const int bn = blockIdx.x * 64;

    u64 acc[4][4];
    #pragma unroll
    for (int p = 0; p < 4; p++)
        #pragma unroll
        for (int n = 0; n < 4; n++) acc[p][n] = 0ULL;

    for (int k0 = 0; k0 < C2; k0 += 16) {
        // A chunk 64m x 16k: float4 loads, scalar STS to [k][m]
        #pragma unroll
        for (int l = 0; l < 2; l++) {
            int idx = tid + l * 128;
            int m = idx >> 2, kq = idx & 3;
            float4 av = *(const float4*)&A[(bm + m) * C2 + k0 + 4 * kq];
            As[(4 * kq + 0) * 68 + m] = av.x;
            As[(4 * kq + 1) * 68 + m] = av.y;
            As[(4 * kq + 2) * 68 + m] = av.z;
            As[(4 * kq + 3) * 68 + m] = av.w;
        }
        // W chunk 16k x 64n: float4 load + float4 STS
        #pragma unroll
        for (int l = 0; l < 2; l++) {
            int idx = tid + l * 128;
            int nq = idx & 15, kw = idx >> 4;
            float4 wv = *(const float4*)&W[(k0 + kw) * C + bn + 4 * nq];
            *(float4*)&Ws[kw * 68 + 4 * nq] = wv;
        }
        __syncthreads();

        #pragma unroll
        for (int k = 0; k < 16; k++) {
            ulonglong2 A01 = *(const ulonglong2*)&As[k * 68 + 8 * ty];     // pairs (m0,m1),(m2,m3)
            ulonglong2 A23 = *(const ulonglong2*)&As[k * 68 + 8 * ty + 4]; // pairs (m4,m5),(m6,m7)
            float4 wv = *(const float4*)&Ws[k * 68 + 4 * tx];
            u64 wd[4];
            wd[0] = pack2(wv.x, wv.x);
            wd[1] = pack2(wv.y, wv.y);
            wd[2] = pack2(wv.z, wv.z);
            wd[3] = pack2(wv.w, wv.w);
            u64 ap[4] = {A01.x, A01.y, A23.x, A23.y};
            #pragma unroll
            for (int p = 0; p < 4; p++) {
                acc[p][0] = fma2(ap[p], wd[0], acc[p][0]);
                acc[p][1] = fma2(ap[p], wd[1], acc[p][1]);
                acc[p][2] = fma2(ap[p], wd[2], acc[p][2]);
                acc[p][3] = fma2(ap[p], wd[3], acc[p][3]);
            }
        }
        __syncthreads();
    }

    float4 bv = *(const float4*)&bias[bn + 4 * tx];
    #pragma unroll
    for (int p = 0; p < 4; p++) {
        float2 f0 = unpack2(acc[p][0]);
        float2 f1 = unpack2(acc[p][1]);
        float2 f2 = unpack2(acc[p][2]);
        float2 f3 = unpack2(acc[p][3]);
        float4 rlo = make_float4(f0.x + bv.x, f1.x + bv.y, f2.x + bv.z, f3.x + bv.w);
        float4 rhi = make_float4(f0.y + bv.x, f1.y + bv.y, f2.y + bv.z, f3.y + bv.w);
        int m = bm + 8 * ty + 2 * p;
        *(float4*)&out[(size_t)m * C + bn + 4 * tx] = rlo;
        *(float4*)&out[(size_t)(m + 1) * C + bn + 4 * tx] = rhi;
    }
}

// ---------------------------------------------------------------------------
// Kernel 2b: Sw[j,h] = subj[j,:] @ W_t  and  Ow[i,h] = obj[i,:] @ W_t.
// ---------------------------------------------------------------------------
__global__ void __launch_bounds__(128)
swow_kernel(const float* __restrict__ subj,
            const float* __restrict__ obj,
            const float* __restrict__ W_t,
            float* __restrict__ swow) {
    int gw = (blockIdx.x * 128 + threadIdx.x) >> 5;   // 0..4095
    int lane = threadIdx.x & 31;
    const float* src = (gw < M) ? subj : obj;
    int row = gw & (M - 1);

    float4 a = make_float4(0.f, 0.f, 0.f, 0.f);
    const float4* wt4 = (const float4*)W_t;
    #pragma unroll
    for (int c = lane; c < C; c += 32) {
        float s = src[row * C + c];
        float4 w = wt4[c];
        a.x += s * w.x; a.y += s * w.y; a.z += s * w.z; a.w += s * w.w;
    }
    #pragma unroll
    for (int m = 16; m >= 1; m >>= 1) {
        a.x += __shfl_xor_sync(0xffffffffu, a.x, m);
        a.y += __shfl_xor_sync(0xffffffffu, a.y, m);
        a.z += __shfl_xor_sync(0xffffffffu, a.z, m);
        a.w += __shfl_xor_sync(0xffffffffu, a.w, m);
    }
    if (lane == 0) ((float4*)swow)[gw] = a;
}

// ---------------------------------------------------------------------------
// Kernel 3a (R7-exact shape): rep = Sw[j]+Ow[i]+b - 2*sum_c min(s,o)*w.
// 128 threads = 16 tx (j, stride-16) x 8 ty (i, stride-8); 4i x 4j x 4h.
// ---------------------------------------------------------------------------
__global__ void __launch_bounds__(128)
rep_exp_kernel(const float* __restrict__ subj,
               const float* __restrict__ obj,
               const float* __restrict__ W_t,
               const float* __restrict__ b_t,
               const float* __restrict__ swow,
               float* __restrict__ attn,
               float* __restrict__ part) {
    __shared__ float s_sh[TJ * CK];     // [jrow][c], swizzled (32KB)
    __shared__ float o_sh[TI * CK];     // [irow][c], swizzled (16KB)
    __shared__ float w_sh[HEADS * C];   // [h][c] = -2*W_t (4KB)

    const int tid = threadIdx.x;
    const int tx = tid & 15;           // j: j0 + tx + 16q
    const int ty = tid >> 4;           // i: i0 + ty + 8p   (0..7)
    const int jt = blockIdx.x;
    const int j0 = jt * TJ;
    const int i0 = blockIdx.y * TI;
    const int b  = blockIdx.z;

    #pragma unroll
    for (int c = tid; c < C; c += 128) {
        float4 wv = *(const float4*)&W_t[c * 4];
        w_sh[0 * C + c] = -2.0f * wv.x;
        w_sh[1 * C + c] = -2.0f * wv.y;
        w_sh[2 * C + c] = -2.0f * wv.z;
        w_sh[3 * C + c] = -2.0f * wv.w;
    }

    u64 acc[4][4][4];
    #pragma unroll
    for (int p = 0; p < 4; p++)
        #pragma unroll
        for (int q = 0; q < 4; q++)
            #pragma unroll
            for (int h = 0; h < 4; h++) acc[p][q][h] = 0ULL;

    const int swj = tx & 7;
    const float* sp[4];
    const float* op[4];
    #pragma unroll
    for (int q = 0; q < 4; q++) sp[q] = s_sh + (tx + 16 * q) * CK;
    #pragma unroll
    for (int p = 0; p < 4; p++) op[p] = o_sh + (ty + 8 * p) * CK;

    for (int ck = 0; ck < C / CK; ck++) {
        const int cbase = ck * CK;
        #pragma unroll
        for (int l = 0; l < 16; l++) {
            int t = tid + l * 128;
            int row = t >> 5;          // 0..63
            int ccg = t & 31;
            int phys = (ccg ^ (row & 7)) << 2;
            float4 sv = *(const float4*)&subj[(b * T + j0 + row) * C + cbase + ccg * 4];
            *(float4*)&s_sh[row * CK + phys] = sv;
        }
        #pragma unroll
        for (int l = 0; l < 8; l++) {
            int t = tid + l * 128;
            int row = t >> 5;          // 0..31
            int ccg = t & 31;
            int phys = (ccg ^ (row & 7)) << 2;
            float4 ov = *(const float4*)&obj[(b * T + i0 + row) * C + cbase + ccg * 4];
            *(float4*)&o_sh[row * CK + phys] = ov;
        }
        __syncthreads();

        const float* wp0 = w_sh + 0 * C + cbase;
        const float* wp1 = w_sh + 1 * C + cbase;
        const float* wp2 = w_sh + 2 * C + cbase;
        const float* wp3 = w_sh + 3 * C + cbase;

        #pragma unroll 1
        for (int g = 0; g < CK / 4; g++) {
            const int gs = ((g ^ swj) << 2);
            const int gi = ((g ^ ty) << 2);
            ulonglong2 S[4], P[4], Wv[4];
            #pragma unroll
            for (int q = 0; q < 4; q++) S[q] = *(const ulonglong2*)(sp[q] + gs);
            #pragma unroll
            for (int p = 0; p < 4; p++) P[p] = *(const ulonglong2*)(op[p] + gi);
            Wv[0] = *(const ulonglong2*)(wp0 + g * 4);
            Wv[1] = *(const ulonglong2*)(wp1 + g * 4);
            Wv[2] = *(const ulonglong2*)(wp2 + g * 4);
            Wv[3] = *(const ulonglong2*)(wp3 + g * 4);

            #pragma unroll
            for (int p = 0; p < 4; p++) {
                #pragma unroll
                for (int q = 0; q < 4; q++) {
                    u64 m0 = fmin2(S[q].x, P[p].x);
                    acc[p][q][0] = fma2(m0, Wv[0].x, acc[p][q][0]);
                    acc[p][q][1] = fma2(m0, Wv[1].x, acc[p][q][1]);
                    acc[p][q][2] = fma2(m0, Wv[2].x, acc[p][q][2]);
                    acc[p][q][3] = fma2(m0, Wv[3].x, acc[p][q][3]);
                    u64 m1 = fmin2(S[q].y, P[p].y);
                    acc[p][q][0] = fma2(m1, Wv[0].y, acc[p][q][0]);
                    acc[p][q][1] = fma2(m1, Wv[1].y, acc[p][q][1]);
                    acc[p][q][2] = fma2(m1, Wv[2].y, acc[p][q][2]);
                    acc[p][q][3] = fma2(m1, Wv[3].y, acc[p][q][3]);
                }
            }
        }
        __syncthreads();
    }

    const float4 btv = *(const float4*)b_t;
    const float4* sw4 = (const float4*)swow;              // rows 0..M-1
    const float4* ow4 = (const float4*)swow + M;          // rows M..

    float4 owv[4];
    #pragma unroll
    for (int p = 0; p < 4; p++) owv[p] = ow4[b * T + i0 + ty + 8 * p];

    #pragma unroll
    for (int p = 0; p < 4; p++) {
        int i = i0 + ty + 8 * p;
        float4 ps = make_float4(0.f, 0.f, 0.f, 0.f);
        float base_x = owv[p].x + btv.x;
        float base_y = owv[p].y + btv.y;
        float base_z = owv[p].z + btv.z;
        float base_w = owv[p].w + btv.w;
        #pragma unroll
        for (int q = 0; q < 4; q++) {
            int j = j0 + tx + 16 * q;
            float4 swv = sw4[b * T + j];
            float2 f0 = unpack2(acc[p][q][0]);
            float2 f1 = unpack2(acc[p][q][1]);
            float2 f2 = unpack2(acc[p][q][2]);
            float2 f3 = unpack2(acc[p][q][3]);
            float4 ev;
            ev.x = __expf(fmaxf(f0.x + f0.y + swv.x + base_x, 0.0f));
            ev.y = __expf(fmaxf(f1.x + f1.y + swv.y + base_y, 0.0f));
            ev.z = __expf(fmaxf(f2.x + f2.y + swv.z + base_z, 0.0f));
            ev.w = __expf(fmaxf(f3.x + f3.y + swv.w + base_w, 0.0f));
            *(float4*)&attn[(((size_t)(b * T + i)) * T + j) * HEADS] = ev;
            ps.x += ev.x; ps.y += ev.y; ps.z += ev.z; ps.w += ev.w;
        }
        #pragma unroll
        for (int m = 8; m >= 1; m >>= 1) {
            ps.x += __shfl_xor_sync(0xffffffffu, ps.x, m);
            ps.y += __shfl_xor_sync(0xffffffffu, ps.y, m);
            ps.z += __shfl_xor_sync(0xffffffffu, ps.z, m);
            ps.w += __shfl_xor_sync(0xffffffffu, ps.w, m);
        }
        if (tx == 0)
            *(float4*)&part[((size_t)(b * T + i) * NJT + jt) * HEADS] = ps;
    }
}

// ---------------------------------------------------------------------------
// Kernel 3b: denominator + normalize + mask; 2 rows per block (shared mask j).
// ---------------------------------------------------------------------------
__global__ void __launch_bounds__(256)
normalize_kernel(const float* __restrict__ part,
                 const int* __restrict__ mask,
                 float* __restrict__ attn) {
    __shared__ float sinv[8];
    const int r = blockIdx.x;          // rows 2r, 2r+1
    const int tid = threadIdx.x;
    const int lane = tid & 31;
    const int wid = tid >> 5;

    if (wid < 2) {
        int row = 2 * r + wid;
        float v = part[row * (NJT * HEADS) + lane];
        v += __shfl_xor_sync(0xffffffffu, v, 4);
        v += __shfl_xor_sync(0xffffffffu, v, 8);
        v += __shfl_xor_sync(0xffffffffu, v, 16);
        if (lane < 4) sinv[wid * 4 + lane] = 1.0f / v;
    }
    __syncthreads();

    const float4 iv0 = make_float4(sinv[0], sinv[1], sinv[2], sinv[3]);
    const float4 iv1 = make_float4(sinv[4], sinv[5], sinv[6], sinv[7]);
    const int bi0 = 2 * r;
    const int b = bi0 >> 9;
    const int mi0 = mask[bi0];
    const int mi1 = mask[bi0 + 1];
    float4* arow0 = (float4*)attn + (size_t)bi0 * T;
    float4* arow1 = arow0 + T;

    #pragma unroll
    for (int rr = 0; rr < 2; rr++) {
        int j = tid + rr * 256;
        int mj = mask[b * T + j];
        float k0 = (mi0 && mj) ? 0.0f : 1.0f;
        float k1 = (mi1 && mj) ? 0.0f : 1.0f;
        float4 v0 = arow0[j];
        float4 v1 = arow1[j];
        v0.x *= iv0.x * k0; v0.y *= iv0.y * k0; v0.z *= iv0.z * k0; v0.w *= iv0.w * k0;
        v1.x *= iv1.x * k1; v1.y *= iv1.y * k1; v1.z *= iv1.z * k1; v1.w *= iv1.w * k1;
        arow0[j] = v0;
        arow1[j] = v1;
    }
}

// ---------------------------------------------------------------------------
extern "C" void kernel_launch(void* const* d_in, const int* in_sizes, int n_in,
                              void* d_out, int out_size) {
    const float* x      = (const float*)d_in[0];
    const float* W_subj = (const float*)d_in[1];
    const float* b_subj = (const float*)d_in[2];
    const float* W_obj  = (const float*)d_in[3];
    const float* b_obj  = (const float*)d_in[4];
    const float* W_t    = (const float*)d_in[5];
    const float* b_t    = (const float*)d_in[6];
    const int*   mask   = (const int*)d_in[7];

    float* out   = (float*)d_out;
    float* xnew  = out;                          // (B,T,2C)
    float* attn  = out + (size_t)M * C2;         // (B,T,T,HEADS)

    float *subj, *obj, *part, *swow;
    cudaGetSymbolAddress((void**)&subj, g_subj);
    cudaGetSymbolAddress((void**)&obj, g_obj);
    cudaGetSymbolAddress((void**)&part, g_part);
    cudaGetSymbolAddress((void**)&swow, g_swow);

    pool_concat_kernel<<<(M * C2 + 255) / 256, 256>>>(x, xnew);

    dim3 gg(C / 64, M / 64, 2);   // (4, 32, 2) = 256 blocks
    gemm_kernel<<<gg, 128>>>(xnew, W_subj, b_subj, W_obj, b_obj, subj, obj);

    swow_kernel<<<(2 * M) / 4, 128>>>(subj, obj, W_t, swow);

    dim3 ga(T / TJ, T / TI, B);   // (8, 16, 4) = 512 blocks
    rep_exp_kernel<<<ga, 128>>>(subj, obj, W_t, b_t, swow, attn, part);

    normalize_kernel<<<M / 2, 256>>>(part, mask, attn);
}